// round 6
// baseline (speedup 1.0000x reference)
#include <cuda_runtime.h>
#include <cuda_bf16.h>
#include <cstddef>

#define DK 64
#define TPB 160             // 5 warps
#define ITEM_BLOCKS 444
#define B_MAX 4096

// Scratch (no cudaMalloc allowed)
__device__ float    g_G1[DK * DK];     // item_W^T item_W   (atomic)
__device__ float    g_G2[DK * DK];     // u_emb^T u_emb     (atomic)
__device__ float    g_posp[B_MAX];     // per-row pos-loss partials
__device__ unsigned g_done = 0;        // last-block election counter

// ---------------------------------------------------------------------------
// One kernel, three block roles + last-block final reduction:
//   [0, ITEM_BLOCKS)               : item Gram (upper-tri 4x4 tiles, 136 thr)
//   [ITEM_BLOCKS, ITEM_BLOCKS+nG2) : user Gram (64 gathered rows per block)
//   [ITEM_BLOCKS+nG2, ...+B)       : pos_data_loss, one block per batch row
__global__ void __launch_bounds__(TPB)
k_fused(const int* __restrict__ uids,
        const int* __restrict__ pos_iids,
        const float* __restrict__ userW,
        const float* __restrict__ itemW,
        const float* __restrict__ h,
        float* __restrict__ out,
        int B, int L, int PAD, int R, int nG2) {
    __shared__ float sm[64 * DK];       // 16 KB tile / wu scratch / reduce
    __shared__ float wsum[TPB / 32];
    __shared__ int   sIsLast;
    const int tid = threadIdx.x;
    const int bid = blockIdx.x;

    if (bid < ITEM_BLOCKS + nG2) {
        // ------------------ Gram path (item or user) ------------------
        const bool isItem = bid < ITEM_BLOCKS;
        int ti = 0, tj = 0;
        const bool active = tid < 136;
        if (active) {                       // upper-tri tile map
            int k = tid, t = 0;
            while (k >= 16 - t) { k -= 16 - t; t++; }
            ti = t; tj = t + k;
        }
        float acc[4][4];
#pragma unroll
        for (int a = 0; a < 4; a++)
#pragma unroll
            for (int b = 0; b < 4; b++) acc[a][b] = 0.f;

        if (isItem) {
            const int n_tiles = (R + 63) / 64;
            for (int t = bid; t < n_tiles; t += ITEM_BLOCKS) {
                const int row0  = t * 64;
                const int valid = min(64, R - row0);
                __syncthreads();
                const float4* src = (const float4*)(itemW + (size_t)row0 * DK);
                float4* dst = (float4*)sm;
                for (int i = tid; i < valid * (DK / 4); i += TPB) dst[i] = src[i];
                __syncthreads();
                if (active) {
                    if (valid == 64) {
#pragma unroll 4
                        for (int r = 0; r < 64; r++) {
                            float4 vi = *(const float4*)&sm[r * DK + ti * 4];
                            float4 vj = *(const float4*)&sm[r * DK + tj * 4];
                            float ai[4] = {vi.x, vi.y, vi.z, vi.w};
                            float aj[4] = {vj.x, vj.y, vj.z, vj.w};
#pragma unroll
                            for (int a = 0; a < 4; a++)
#pragma unroll
                                for (int b = 0; b < 4; b++) acc[a][b] += ai[a] * aj[b];
                        }
                    } else {
                        for (int r = 0; r < valid; r++) {
                            float4 vi = *(const float4*)&sm[r * DK + ti * 4];
                            float4 vj = *(const float4*)&sm[r * DK + tj * 4];
                            float ai[4] = {vi.x, vi.y, vi.z, vi.w};
                            float aj[4] = {vj.x, vj.y, vj.z, vj.w};
#pragma unroll
                            for (int a = 0; a < 4; a++)
#pragma unroll
                                for (int b = 0; b < 4; b++) acc[a][b] += ai[a] * aj[b];
                        }
                    }
                }
            }
        } else {
            const int base = (bid - ITEM_BLOCKS) * 64;
            for (int i = tid; i < 64 * DK; i += TPB) {
                int u = base + (i >> 6);
                sm[i] = (u < B) ? userW[(size_t)uids[u] * DK + (i & 63)] : 0.f;
            }
            __syncthreads();
            if (active) {
#pragma unroll 4
                for (int r = 0; r < 64; r++) {
                    float4 vi = *(const float4*)&sm[r * DK + ti * 4];
                    float4 vj = *(const float4*)&sm[r * DK + tj * 4];
                    float ai[4] = {vi.x, vi.y, vi.z, vi.w};
                    float aj[4] = {vj.x, vj.y, vj.z, vj.w};
#pragma unroll
                    for (int a = 0; a < 4; a++)
#pragma unroll
                        for (int b = 0; b < 4; b++) acc[a][b] += ai[a] * aj[b];
                }
            }
        }
        if (active) {
            float* G = isItem ? g_G1 : g_G2;
#pragma unroll
            for (int a = 0; a < 4; a++)
#pragma unroll
                for (int b = 0; b < 4; b++)
                    atomicAdd(&G[(ti * 4 + a) * DK + tj * 4 + b], acc[a][b]);
            if (ti != tj) {
#pragma unroll
                for (int a = 0; a < 4; a++)
#pragma unroll
                    for (int b = 0; b < 4; b++)
                        atomicAdd(&G[(tj * 4 + b) * DK + ti * 4 + a], acc[a][b]);
            }
        }
    } else {
        // ------------------ hpq: one block per batch row b ------------------
        const int b    = bid - ITEM_BLOCKS - nG2;
        const int lane = tid & 31, w = tid >> 5;
        const int sub  = lane & 7, grp = lane >> 3;

        // wu = userW[uids[b]] * h, computed in-block
        if (tid < DK / 4) {
            float4 hu = ((const float4*)h)[tid];
            float4 uu = ((const float4*)(userW + (size_t)uids[b] * DK))[tid];
            float4 r;
            r.x = hu.x * uu.x; r.y = hu.y * uu.y;
            r.z = hu.z * uu.z; r.w = hu.w * uu.w;
            ((float4*)sm)[tid] = r;
        }
        __syncthreads();

        const float4 w0 = ((const float4*)sm)[sub];        // bytes [0,128)
        const float4 w1 = ((const float4*)sm)[sub + 8];    // bytes [128,256)
        const int* ids = pos_iids + (size_t)b * L;

        float loss = 0.f;
        const int per_step = (TPB / 32) * 16;              // 80 items/step
        const int nsteps = (L + per_step - 1) / per_step;  // 3 for L=200
        for (int s = 0; s < nsteps; s++) {
            const int l0 = s * per_step + (w * 4 + grp) * 4;
            int4 ii;
            if (l0 + 3 < L) {
                ii = *(const int4*)&ids[l0];               // 16B-aligned
            } else {
                ii.x = (l0     < L) ? ids[l0]     : PAD;
                ii.y = (l0 + 1 < L) ? ids[l0 + 1] : PAD;
                ii.z = (l0 + 2 < L) ? ids[l0 + 2] : PAD;
                ii.w = (l0 + 3 < L) ? ids[l0 + 3] : PAD;
            }
            const int iid[4] = {ii.x, ii.y, ii.z, ii.w};
            float4 va[4], vb[4];
#pragma unroll
            for (int t = 0; t < 4; t++) {
                const float4* row = (const float4*)(itemW + (size_t)iid[t] * DK);
                va[t] = row[sub];
                vb[t] = row[sub + 8];
            }
            float d[4];
#pragma unroll
            for (int t = 0; t < 4; t++)
                d[t] = va[t].x * w0.x + va[t].y * w0.y + va[t].z * w0.z + va[t].w * w0.w
                     + vb[t].x * w1.x + vb[t].y * w1.y + vb[t].z * w1.z + vb[t].w * w1.w;
#pragma unroll
            for (int off = 4; off; off >>= 1)
#pragma unroll
                for (int t = 0; t < 4; t++)
                    d[t] += __shfl_xor_sync(0xffffffffu, d[t], off);
            if (sub == 0) {
#pragma unroll
                for (int t = 0; t < 4; t++)
                    if (l0 + t < L && iid[t] != PAD)
                        loss += 0.9f * d[t] * d[t] - 2.0f * d[t];
            }
        }
#pragma unroll
        for (int off = 16; off; off >>= 1)
            loss += __shfl_xor_sync(0xffffffffu, loss, off);
        if (lane == 0) wsum[w] = loss;
        __syncthreads();
        if (tid == 0) {
            float s = 0.f;
#pragma unroll
            for (int k = 0; k < TPB / 32; k++) s += wsum[k];
            g_posp[b] = s;
        }
    }

    // ------------------ last-block final reduction ------------------
    const unsigned total = ITEM_BLOCKS + nG2 + B;
    __threadfence();
    __syncthreads();
    if (tid == 0) {
        unsigned t = atomicAdd(&g_done, 1u);
        sIsLast = (t == total - 1);
    }
    __syncthreads();
    if (sIsLast) {
        __threadfence();
        double s = 0.0;
        for (int e = tid; e < DK * DK; e += TPB)
            s += (double)g_G1[e] * (double)g_G2[e] *
                 (double)(h[e >> 6] * h[e & 63]);
        s *= 0.1;
        for (int i = tid; i < B; i += TPB)
            s += (double)g_posp[i];

        double* red = (double*)sm;
        red[tid] = s;
        __syncthreads();
        if (tid < 32) {
            double v = red[tid];
#pragma unroll
            for (int k = 1; k < TPB / 32; k++) v += red[tid + 32 * k];
#pragma unroll
            for (int off = 16; off; off >>= 1)
                v += __shfl_xor_sync(0xffffffffu, v, off);
            if (tid == 0) {
                out[0] = (float)v;
                g_done = 0;                 // reset for next graph replay
            }
        }
    }
}

// ---------------------------------------------------------------------------
extern "C" void kernel_launch(void* const* d_in, const int* in_sizes, int n_in,
                              void* d_out, int out_size) {
    const int*   uids     = (const int*)d_in[0];
    const int*   pos_iids = (const int*)d_in[1];
    const float* user_W   = (const float*)d_in[2];
    const float* item_W   = (const float*)d_in[3];
    const float* h        = (const float*)d_in[4];
    float* out = (float*)d_out;

    const int B   = in_sizes[0];          // 4096
    const int L   = in_sizes[1] / B;      // 200
    const int R   = in_sizes[3] / DK;     // 100001 item rows
    const int PAD = R - 1;                // padding item id
    const int nG2 = (B + 63) / 64;        // user-gram blocks

    void *pG1 = nullptr, *pG2 = nullptr;
    cudaGetSymbolAddress(&pG1, g_G1);
    cudaGetSymbolAddress(&pG2, g_G2);
    cudaMemsetAsync(pG1, 0, DK * DK * sizeof(float));
    cudaMemsetAsync(pG2, 0, DK * DK * sizeof(float));

    k_fused<<<ITEM_BLOCKS + nG2 + B, TPB>>>(uids, pos_iids, user_W, item_W, h,
                                            out, B, L, PAD, R, nG2);
}